// round 2
// baseline (speedup 1.0000x reference)
#include <cuda_runtime.h>
#include <math.h>

#define BB 16
#define NN 1024
#define FIN 64
#define HH 256
#define NEGV (-9e15f)
#define LALPHA 0.2f

// ---------------- scratch (device globals: no allocation allowed) ----------
__device__ __align__(256) float g_x[BB * NN * HH];     // 16 MB
__device__ __align__(256) float g_h[BB * NN * HH];     // 16 MB
__device__ __align__(256) float g_s1[BB * NN];
__device__ __align__(256) float g_s2[BB * NN];
__device__ __align__(256) float g_m[BB * NN];
__device__ __align__(256) float g_linv[BB * NN];
__device__ __align__(256) float g_sum[BB * HH];
__device__ __align__(256) float g_max[BB * HH];

// ---------------- generic tiled SGEMM: C = A[M,K] @ B[K,Nc] (+bias) --------
// BM=128, BN=64, BK=16, 256 threads, micro-tile 8x4.
__global__ void __launch_bounds__(256) sgemm_kernel(
    const float* __restrict__ A, const float* __restrict__ Bw,
    const float* __restrict__ bias, float* __restrict__ C,
    int M, int K, int Nc)
{
    __shared__ float As[16][128];   // transposed A tile
    __shared__ float Bs[16][64];

    int tid = threadIdx.x;
    int tx = tid & 15;        // 0..15 -> col group (4 cols)
    int ty = tid >> 4;        // 0..15 -> row group (8 rows)
    int m0 = blockIdx.y * 128;
    int n0 = blockIdx.x * 64;

    float acc[8][4];
#pragma unroll
    for (int r = 0; r < 8; r++)
#pragma unroll
        for (int c = 0; c < 4; c++) acc[r][c] = 0.f;

    for (int k0 = 0; k0 < K; k0 += 16) {
        // load A tile 128x16 (transposed into As[k][m])
#pragma unroll
        for (int t = 0; t < 2; t++) {
            int lin = tid * 2 + t;            // 0..511
            int r = lin >> 2;                 // 0..127
            int c4 = (lin & 3) * 4;           // 0,4,8,12
            float4 v = *(const float4*)(A + (size_t)(m0 + r) * K + k0 + c4);
            As[c4 + 0][r] = v.x;
            As[c4 + 1][r] = v.y;
            As[c4 + 2][r] = v.z;
            As[c4 + 3][r] = v.w;
        }
        // load B tile 16x64
        {
            int r = tid >> 4;
            int c4 = (tid & 15) * 4;
            *(float4*)&Bs[r][c4] =
                *(const float4*)(Bw + (size_t)(k0 + r) * Nc + n0 + c4);
        }
        __syncthreads();

#pragma unroll
        for (int k = 0; k < 16; k++) {
            float4 a0 = *(float4*)&As[k][ty * 8];
            float4 a1 = *(float4*)&As[k][ty * 8 + 4];
            float4 bv = *(float4*)&Bs[k][tx * 4];
            float av[8] = {a0.x, a0.y, a0.z, a0.w, a1.x, a1.y, a1.z, a1.w};
            float bvv[4] = {bv.x, bv.y, bv.z, bv.w};
#pragma unroll
            for (int r = 0; r < 8; r++)
#pragma unroll
                for (int c = 0; c < 4; c++)
                    acc[r][c] = fmaf(av[r], bvv[c], acc[r][c]);
        }
        __syncthreads();
    }

#pragma unroll
    for (int r = 0; r < 8; r++) {
        int row = m0 + ty * 8 + r;
        float4 v;
        v.x = acc[r][0]; v.y = acc[r][1]; v.z = acc[r][2]; v.w = acc[r][3];
        if (bias) {
            const float* bp = bias + n0 + tx * 4;
            v.x += bp[0]; v.y += bp[1]; v.z += bp[2]; v.w += bp[3];
        }
        *(float4*)(C + (size_t)row * Nc + n0 + tx * 4) = v;
    }
}

// ---------------- s1 = h . a1, s2 = h . a2 (one warp per row) --------------
__global__ void rowdot_kernel(const float* __restrict__ h,
                              const float* __restrict__ a1,
                              const float* __restrict__ a2)
{
    int warp = (blockIdx.x * blockDim.x + threadIdx.x) >> 5;
    int lane = threadIdx.x & 31;
    if (warp >= BB * NN) return;

    const float* hr = h + (size_t)warp * HH + lane * 8;
    float4 h0 = *(const float4*)hr;
    float4 h1 = *(const float4*)(hr + 4);
    float4 p0 = *(const float4*)(a1 + lane * 8);
    float4 p1 = *(const float4*)(a1 + lane * 8 + 4);
    float4 q0 = *(const float4*)(a2 + lane * 8);
    float4 q1 = *(const float4*)(a2 + lane * 8 + 4);

    float d1 = h0.x * p0.x + h0.y * p0.y + h0.z * p0.z + h0.w * p0.w +
               h1.x * p1.x + h1.y * p1.y + h1.z * p1.z + h1.w * p1.w;
    float d2 = h0.x * q0.x + h0.y * q0.y + h0.z * q0.z + h0.w * q0.w +
               h1.x * q1.x + h1.y * q1.y + h1.z * q1.z + h1.w * q1.w;
#pragma unroll
    for (int off = 16; off; off >>= 1) {
        d1 += __shfl_xor_sync(0xffffffffu, d1, off);
        d2 += __shfl_xor_sync(0xffffffffu, d2, off);
    }
    if (lane == 0) {
        g_s1[warp] = d1;
        g_s2[warp] = d2;
    }
}

// ---------------- softmax stats per row: m, 1/l (one warp per row) ---------
__global__ void stats_kernel(const float* __restrict__ adj)
{
    int warp_in = threadIdx.x >> 5;
    int lane = threadIdx.x & 31;
    int row = blockIdx.x * 8 + warp_in;           // row in [0, BB*NN)
    int b = row >> 10;

    const float* ar = adj + (size_t)row * NN;
    const float* s2b = g_s2 + (b << 10);
    float s1v = g_s1[row];

    float e[32];
    float m = -INFINITY;
#pragma unroll
    for (int jj = 0; jj < 32; jj++) {
        int j = jj * 32 + lane;
        float a = ar[j];
        float t = s1v + s2b[j];
        t = (t >= 0.f) ? t : LALPHA * t;
        t = (a > 0.f) ? t : NEGV;
        e[jj] = t;
        m = fmaxf(m, t);
    }
#pragma unroll
    for (int off = 16; off; off >>= 1)
        m = fmaxf(m, __shfl_xor_sync(0xffffffffu, m, off));

    float l = 0.f;
#pragma unroll
    for (int jj = 0; jj < 32; jj++) l += __expf(e[jj] - m);
#pragma unroll
    for (int off = 16; off; off >>= 1)
        l += __shfl_xor_sync(0xffffffffu, l, off);

    if (lane == 0) {
        g_m[row] = m;
        g_linv[row] = 1.f / l;
    }
}

// ---------------- attention: out = relu( softmax(masked e) @ h ) -----------
// One block per (b, 64-row tile). C tile 64x256, P tiles 64x64 computed on
// the fly from adj/s1/s2/m. Epilogue folds 1/l and ReLU.
__global__ void __launch_bounds__(256, 2) attn_kernel(
    const float* __restrict__ adj, const float* __restrict__ h,
    float* __restrict__ out)
{
    int blk = blockIdx.x;          // 0..255
    int b = blk >> 4;
    int i0 = (blk & 15) << 6;

    int tid = threadIdx.x;
    int tx = tid & 15;             // col group: 16 cols
    int ty = tid >> 4;             // row group: 4 rows

    __shared__ float Pt[64][64];   // [k][row]
    __shared__ float Hs[8][HH];
    __shared__ float s1s[64], ms[64], s2s[64];

    if (tid < 64) {
        s1s[tid] = g_s1[b * NN + i0 + tid];
        ms[tid] = g_m[b * NN + i0 + tid];
    }

    float acc[4][16];
#pragma unroll
    for (int r = 0; r < 4; r++)
#pragma unroll
        for (int c = 0; c < 16; c++) acc[r][c] = 0.f;

    const float* adjb = adj + ((size_t)b * NN + i0) * NN;
    const float* hb = h + (size_t)b * NN * HH;

    for (int j0 = 0; j0 < NN; j0 += 64) {
        __syncthreads();               // protect s2s/Pt from previous iter
        if (tid < 64) s2s[tid] = g_s2[b * NN + j0 + tid];
        __syncthreads();

        // build P^T tile: Pt[c][r] = mask ? exp(leaky(s1_r+s2_c) - m_r) : 0
#pragma unroll
        for (int t = 0; t < 4; t++) {
            int lin = tid + t * 256;   // 0..1023
            int r = lin >> 4;          // 0..63
            int c4 = (lin & 15) << 2;  // 0..60
            float4 av = *(const float4*)(adjb + (size_t)r * NN + j0 + c4);
            float sv = s1s[r], mv = ms[r];
            float e0 = sv + s2s[c4 + 0]; e0 = (e0 >= 0.f) ? e0 : LALPHA * e0;
            float e1 = sv + s2s[c4 + 1]; e1 = (e1 >= 0.f) ? e1 : LALPHA * e1;
            float e2 = sv + s2s[c4 + 2]; e2 = (e2 >= 0.f) ? e2 : LALPHA * e2;
            float e3 = sv + s2s[c4 + 3]; e3 = (e3 >= 0.f) ? e3 : LALPHA * e3;
            Pt[c4 + 0][r] = (av.x > 0.f) ? __expf(e0 - mv) : 0.f;
            Pt[c4 + 1][r] = (av.y > 0.f) ? __expf(e1 - mv) : 0.f;
            Pt[c4 + 2][r] = (av.z > 0.f) ? __expf(e2 - mv) : 0.f;
            Pt[c4 + 3][r] = (av.w > 0.f) ? __expf(e3 - mv) : 0.f;
        }
        __syncthreads();

#pragma unroll
        for (int k0 = 0; k0 < 64; k0 += 8) {
            // load H chunk 8x256
#pragma unroll
            for (int t = 0; t < 2; t++) {
                int lin = tid + t * 256;   // 0..511
                int r = lin >> 6;          // 0..7
                int c4 = (lin & 63) << 2;  // 0..252
                *(float4*)&Hs[r][c4] =
                    *(const float4*)(hb + (size_t)(j0 + k0 + r) * HH + c4);
            }
            __syncthreads();
#pragma unroll
            for (int k = 0; k < 8; k++) {
                float4 pa = *(float4*)&Pt[k0 + k][ty * 4];
                float4 b0 = *(float4*)&Hs[k][tx * 16];
                float4 b1 = *(float4*)&Hs[k][tx * 16 + 4];
                float4 b2 = *(float4*)&Hs[k][tx * 16 + 8];
                float4 b3 = *(float4*)&Hs[k][tx * 16 + 12];
                float pav[4] = {pa.x, pa.y, pa.z, pa.w};
                float bv[16] = {b0.x, b0.y, b0.z, b0.w,
                                b1.x, b1.y, b1.z, b1.w,
                                b2.x, b2.y, b2.z, b2.w,
                                b3.x, b3.y, b3.z, b3.w};
#pragma unroll
                for (int r = 0; r < 4; r++)
#pragma unroll
                    for (int c = 0; c < 16; c++)
                        acc[r][c] = fmaf(pav[r], bv[c], acc[r][c]);
            }
            __syncthreads();
        }
    }

    // epilogue: * (1/l), ReLU, store
#pragma unroll
    for (int r = 0; r < 4; r++) {
        int row = i0 + ty * 4 + r;
        float li = g_linv[b * NN + row];
        float* op = out + ((size_t)b * NN + row) * HH + tx * 16;
#pragma unroll
        for (int c = 0; c < 16; c += 4) {
            float4 v;
            v.x = fmaxf(acc[r][c + 0] * li, 0.f);
            v.y = fmaxf(acc[r][c + 1] * li, 0.f);
            v.z = fmaxf(acc[r][c + 2] * li, 0.f);
            v.w = fmaxf(acc[r][c + 3] * li, 0.f);
            *(float4*)(op + c) = v;
        }
    }
}

// ---------------- pooling -------------------------------------------------
__global__ void zero_pool_kernel()
{
    int i = blockIdx.x * blockDim.x + threadIdx.x;
    if (i < BB * HH) {
        g_sum[i] = 0.f;
        g_max[i] = 0.f;   // x >= 0 after ReLU, so 0 is a valid max identity
    }
}

__global__ void pool_kernel(const float* __restrict__ x)
{
    int b = blockIdx.x >> 3;
    int seg = blockIdx.x & 7;
    int t = threadIdx.x;   // 0..255 = feature
    const float* xb = x + ((size_t)b * NN + seg * 128) * HH + t;
    float s = 0.f, mx = 0.f;
#pragma unroll 4
    for (int i = 0; i < 128; i++) {
        float v = xb[(size_t)i * HH];
        s += v;
        mx = fmaxf(mx, v);
    }
    atomicAdd(&g_sum[b * HH + t], s);
    atomicMax((int*)&g_max[b * HH + t], __float_as_int(mx));
}

// ---------------- tiny 2-layer MLP on pooled features ----------------------
__global__ void mlp_kernel(const float* __restrict__ W1,
                           const float* __restrict__ b1,
                           const float* __restrict__ W2,
                           const float* __restrict__ b2,
                           float* __restrict__ gout)
{
    __shared__ float p[HH];
    __shared__ float y1[HH];
    int b = blockIdx.x, t = threadIdx.x;

    p[t] = g_sum[b * HH + t] * (1.f / (float)NN) + g_max[b * HH + t];
    __syncthreads();

    float acc = b1[t];
#pragma unroll 4
    for (int k = 0; k < HH; k++)
        acc = fmaf(p[k], W1[(size_t)k * HH + t], acc);
    y1[t] = fmaxf(acc, 0.f);
    __syncthreads();

    float acc2 = b2[t];
#pragma unroll 4
    for (int k = 0; k < HH; k++)
        acc2 = fmaf(y1[k], W2[(size_t)k * HH + t], acc2);
    gout[b * HH + t] = acc2;
}

// ---------------- launch --------------------------------------------------
extern "C" void kernel_launch(void* const* d_in, const int* in_sizes, int n_in,
                              void* d_out, int out_size)
{
    const float* nf   = (const float*)d_in[0];
    const float* adj  = (const float*)d_in[1];
    const float* embW = (const float*)d_in[2];
    const float* embb = (const float*)d_in[3];
    const float* W0   = (const float*)d_in[4];
    const float* a10  = (const float*)d_in[5];
    const float* a20  = (const float*)d_in[6];
    const float* W1   = (const float*)d_in[7];
    const float* a11  = (const float*)d_in[8];
    const float* a21  = (const float*)d_in[9];
    const float* gW1  = (const float*)d_in[10];
    const float* gb1  = (const float*)d_in[11];
    const float* gW2  = (const float*)d_in[12];
    const float* gb2  = (const float*)d_in[13];

    float* outx = (float*)d_out;
    float* outg = outx + (size_t)BB * NN * HH;

    float *xp = nullptr, *hp = nullptr;
    cudaGetSymbolAddress((void**)&xp, g_x);
    cudaGetSymbolAddress((void**)&hp, g_h);

    const int M = BB * NN;
    dim3 gemm_grid(HH / 64, M / 128);

    // embed: x = nf @ embW + embb
    sgemm_kernel<<<gemm_grid, 256>>>(nf, embW, embb, xp, M, FIN, HH);

    // ---- GAT layer 0 ----
    sgemm_kernel<<<gemm_grid, 256>>>(xp, W0, nullptr, hp, M, HH, HH);
    rowdot_kernel<<<M / 8, 256>>>(hp, a10, a20);
    stats_kernel<<<M / 8, 256>>>(adj);
    attn_kernel<<<BB * (NN / 64), 256>>>(adj, hp, xp);

    // ---- GAT layer 1 ----
    sgemm_kernel<<<gemm_grid, 256>>>(xp, W1, nullptr, hp, M, HH, HH);
    rowdot_kernel<<<M / 8, 256>>>(hp, a11, a21);
    stats_kernel<<<M / 8, 256>>>(adj);
    attn_kernel<<<BB * (NN / 64), 256>>>(adj, hp, outx);

    // ---- pooling + MLP ----
    zero_pool_kernel<<<(BB * HH + 255) / 256, 256>>>();
    pool_kernel<<<BB * 8, 256>>>(outx);
    mlp_kernel<<<BB, 256>>>(gW1, gb1, gW2, gb2, outg);
}

// round 7
// speedup vs baseline: 3.9257x; 3.9257x over previous
#include <cuda_runtime.h>
#include <cuda_bf16.h>
#include <math.h>
#include <stdint.h>

#define BB 16
#define NN 1024
#define FIN 64
#define HH 256
#define NEGV (-9e15f)
#define LALPHA 0.2f

typedef __nv_bfloat16 bf16;

// ---------------- scratch (device globals: no allocation allowed) ----------
__device__ __align__(256) float g_h[BB * NN * HH];          // h fp32 (rowdot)
__device__ __align__(256) bf16 g_ahi[BB * NN * HH];         // split buf A hi
__device__ __align__(256) bf16 g_alo[BB * NN * HH];
__device__ __align__(256) bf16 g_chi[BB * NN * HH];         // split buf C hi
__device__ __align__(256) bf16 g_clo[BB * NN * HH];
__device__ __align__(256) bf16 g_bhi[BB * NN * HH];         // h bf16 (attn B)
__device__ __align__(256) bf16 g_blo[BB * NN * HH];
__device__ __align__(256) bf16 g_whi[HH * HH];              // weight split
__device__ __align__(256) bf16 g_wlo[HH * HH];
__device__ __align__(256) uint32_t g_adjbits[BB * NN * (NN / 32)];  // 2 MB
__device__ __align__(256) float g_s1[BB * NN];
__device__ __align__(256) float g_s2[BB * NN];
__device__ __align__(256) float g_m[BB * NN];
__device__ __align__(256) float g_linv[BB * NN];
__device__ __align__(256) float g_sum[BB * HH];
__device__ __align__(256) float g_max[BB * HH];

// ---------------- helpers --------------------------------------------------
__device__ __forceinline__ uint32_t swz(uint32_t o) {
    return o ^ ((o >> 3) & 0x70);
}
__device__ __forceinline__ uint32_t su32(const void* p) {
    uint32_t a;
    asm("{ .reg .u64 t; cvta.to.shared.u64 t, %1; cvt.u32.u64 %0, t; }"
        : "=r"(a) : "l"(p));
    return a;
}
__device__ __forceinline__ void ldsm4(uint32_t addr, uint32_t* r) {
    asm volatile("ldmatrix.sync.aligned.m8n8.x4.shared.b16 {%0,%1,%2,%3}, [%4];"
                 : "=r"(r[0]), "=r"(r[1]), "=r"(r[2]), "=r"(r[3]) : "r"(addr));
}
__device__ __forceinline__ void ldsm4t(uint32_t addr, uint32_t* r) {
    asm volatile("ldmatrix.sync.aligned.m8n8.x4.trans.shared.b16 {%0,%1,%2,%3}, [%4];"
                 : "=r"(r[0]), "=r"(r[1]), "=r"(r[2]), "=r"(r[3]) : "r"(addr));
}
__device__ __forceinline__ void mma16816(float* c, const uint32_t* a,
                                         const uint32_t* b) {
    asm volatile(
        "mma.sync.aligned.m16n8k16.row.col.f32.bf16.bf16.f32 "
        "{%0,%1,%2,%3}, {%4,%5,%6,%7}, {%8,%9}, {%0,%1,%2,%3};"
        : "+f"(c[0]), "+f"(c[1]), "+f"(c[2]), "+f"(c[3])
        : "r"(a[0]), "r"(a[1]), "r"(a[2]), "r"(a[3]), "r"(b[0]), "r"(b[1]));
}

// warp mma over one 64-k chunk: A tile [128][64] bf16 (swz 128B rows),
// B panel [64][64] bf16 (swz 128B rows). 3-pass hi/lo split.
__device__ __forceinline__ void mma_chunk(uint32_t aHi, uint32_t aLo,
                                          uint32_t bHi, uint32_t bLo,
                                          int wm, int lane,
                                          float acc[2][8][4])
{
    int rA = lane & 15;
    int cA = (lane >> 4) * 16;
#pragma unroll
    for (int ks = 0; ks < 4; ks++) {
        uint32_t ah[2][4], al[2][4], bb[4][4];
#pragma unroll
        for (int h = 0; h < 2; h++) {
            uint32_t off = swz((uint32_t)(wm * 32 + h * 16 + rA) * 128 +
                               ks * 32 + cA);
            ldsm4(aHi + off, ah[h]);
            ldsm4(aLo + off, al[h]);
        }
#pragma unroll
        for (int t = 0; t < 4; t++) {
            uint32_t off = swz((uint32_t)(ks * 16 + rA) * 128 + t * 32 + cA);
            ldsm4t(bHi + off, bb[t]);
        }
#pragma unroll
        for (int h = 0; h < 2; h++)
#pragma unroll
            for (int t = 0; t < 4; t++) {
                mma16816(acc[h][2 * t], ah[h], bb[t]);         // hh
                mma16816(acc[h][2 * t + 1], ah[h], bb[t] + 2);
                mma16816(acc[h][2 * t], al[h], bb[t]);         // lo*hi
                mma16816(acc[h][2 * t + 1], al[h], bb[t] + 2);
            }
#pragma unroll
        for (int t = 0; t < 4; t++) {
            uint32_t off = swz((uint32_t)(ks * 16 + rA) * 128 + t * 32 + cA);
            ldsm4t(bLo + off, bb[t]);
        }
#pragma unroll
        for (int h = 0; h < 2; h++)
#pragma unroll
            for (int t = 0; t < 4; t++) {
                mma16816(acc[h][2 * t], ah[h], bb[t]);         // hi*lo
                mma16816(acc[h][2 * t + 1], ah[h], bb[t] + 2);
            }
    }
}

__device__ __forceinline__ void split2(float v0, float v1, uint32_t& hw,
                                       uint32_t& lw) {
    __nv_bfloat162 h2 = __floats2bfloat162_rn(v0, v1);
    float r0 = v0 - __bfloat162float(h2.x);
    float r1 = v1 - __bfloat162float(h2.y);
    __nv_bfloat162 l2 = __floats2bfloat162_rn(r0, r1);
    hw = *(uint32_t*)&h2;
    lw = *(uint32_t*)&l2;
}

// ---------------- prep kernels ---------------------------------------------
__global__ void packbits_kernel(const float* __restrict__ adj,
                                uint32_t* __restrict__ bits)
{
    int row = (blockIdx.x * blockDim.x + threadIdx.x) >> 5;
    int lane = threadIdx.x & 31;
    if (row >= BB * NN) return;
    const float* ar = adj + (size_t)row * NN;
    uint32_t myword = 0;
#pragma unroll
    for (int wd = 0; wd < 32; wd++) {
        uint32_t v = __ballot_sync(0xffffffffu, ar[wd * 32 + lane] > 0.f);
        if (lane == wd) myword = v;
    }
    bits[(size_t)row * 32 + lane] = myword;
}

__global__ void split_kernel(const float* __restrict__ X,
                             bf16* __restrict__ Xh, bf16* __restrict__ Xl,
                             int n4)
{
    int i = blockIdx.x * blockDim.x + threadIdx.x;
    if (i >= n4) return;
    float4 v = *(const float4*)(X + (size_t)i * 4);
    uint2 hw, lw;
    split2(v.x, v.y, hw.x, lw.x);
    split2(v.z, v.w, hw.y, lw.y);
    *(uint2*)(Xh + (size_t)i * 4) = hw;
    *(uint2*)(Xl + (size_t)i * 4) = lw;
}

// ---------------- GEMM: C[M,256] = A[M,K] @ B[K,256] (+bias) ---------------
// Outputs: optional fp32 C, + bf16 hi/lo split of C.
__global__ void __launch_bounds__(512, 1) gemm_mma_kernel(
    const bf16* __restrict__ Ah, const bf16* __restrict__ Al,
    const bf16* __restrict__ Bh, const bf16* __restrict__ Bl,
    const float* __restrict__ bias, float* __restrict__ Cf,
    bf16* __restrict__ Chi, bf16* __restrict__ Clo, int K)
{
    extern __shared__ __align__(1024) char smem[];
    const int A_HI = 0, A_LO = 16384, B_HI = 32768, B_LO = 65536;
    uint32_t sb = su32(smem);
    int tid = threadIdx.x, lane = tid & 31, w = tid >> 5;
    int wm = w >> 2, wn = w & 3;
    int m0 = blockIdx.x * 128;

    float acc[2][8][4];
#pragma unroll
    for (int h = 0; h < 2; h++)
#pragma unroll
        for (int t = 0; t < 8; t++)
#pragma unroll
            for (int e = 0; e < 4; e++) acc[h][t][e] = 0.f;

    for (int k0 = 0; k0 < K; k0 += 64) {
        __syncthreads();
        // A tile 128x64
#pragma unroll
        for (int i = tid; i < 1024; i += 512) {
            int r = i >> 3, c = i & 7;
            size_t g = (size_t)(m0 + r) * K + k0 + c * 8;
            uint32_t so = swz(r * 128 + c * 16);
            *(uint4*)(smem + A_HI + so) = *(const uint4*)(Ah + g);
            *(uint4*)(smem + A_LO + so) = *(const uint4*)(Al + g);
        }
        // B tile 64x256 -> 4 panels of [64][64]
#pragma unroll
        for (int i = tid; i < 2048; i += 512) {
            int r = i >> 5, c32 = i & 31;
            int p = c32 >> 3, cc = c32 & 7;
            size_t g = (size_t)(k0 + r) * 256 + c32 * 8;
            uint32_t so = p * 8192 + swz(r * 128 + cc * 16);
            *(uint4*)(smem + B_HI + so) = *(const uint4*)(Bh + g);
            *(uint4*)(smem + B_LO + so) = *(const uint4*)(Bl + g);
        }
        __syncthreads();
        mma_chunk(sb + A_HI, sb + A_LO, sb + B_HI + wn * 8192,
                  sb + B_LO + wn * 8192, wm, lane, acc);
    }

    // epilogue
    int grp = lane >> 2, qp = lane & 3;
#pragma unroll
    for (int h = 0; h < 2; h++) {
        int mA = m0 + wm * 32 + h * 16 + grp;
#pragma unroll
        for (int t = 0; t < 8; t++) {
            int n = wn * 64 + t * 8 + qp * 2;
            float b0 = bias ? bias[n] : 0.f;
            float b1 = bias ? bias[n + 1] : 0.f;
            float v00 = acc[h][t][0] + b0, v01 = acc[h][t][1] + b1;
            float v10 = acc[h][t][2] + b0, v11 = acc[h][t][3] + b1;
            size_t o0 = (size_t)mA * HH + n;
            size_t o1 = (size_t)(mA + 8) * HH + n;
            if (Cf) {
                float2 f0 = {v00, v01}, f1 = {v10, v11};
                *(float2*)(Cf + o0) = f0;
                *(float2*)(Cf + o1) = f1;
            }
            uint32_t hw, lw;
            split2(v00, v01, hw, lw);
            *(uint32_t*)(Chi + o0) = hw;
            *(uint32_t*)(Clo + o0) = lw;
            split2(v10, v11, hw, lw);
            *(uint32_t*)(Chi + o1) = hw;
            *(uint32_t*)(Clo + o1) = lw;
        }
    }
}

// ---------------- s1 = h.a1, s2 = h.a2 (one warp per row) ------------------
__global__ void rowdot_kernel(const float* __restrict__ h,
                              const float* __restrict__ a1,
                              const float* __restrict__ a2)
{
    int warp = (blockIdx.x * blockDim.x + threadIdx.x) >> 5;
    int lane = threadIdx.x & 31;
    if (warp >= BB * NN) return;
    const float* hr = h + (size_t)warp * HH + lane * 8;
    float4 h0 = *(const float4*)hr;
    float4 h1 = *(const float4*)(hr + 4);
    float4 p0 = *(const float4*)(a1 + lane * 8);
    float4 p1 = *(const float4*)(a1 + lane * 8 + 4);
    float4 q0 = *(const float4*)(a2 + lane * 8);
    float4 q1 = *(const float4*)(a2 + lane * 8 + 4);
    float d1 = h0.x * p0.x + h0.y * p0.y + h0.z * p0.z + h0.w * p0.w +
               h1.x * p1.x + h1.y * p1.y + h1.z * p1.z + h1.w * p1.w;
    float d2 = h0.x * q0.x + h0.y * q0.y + h0.z * q0.z + h0.w * q0.w +
               h1.x * q1.x + h1.y * q1.y + h1.z * q1.z + h1.w * q1.w;
#pragma unroll
    for (int off = 16; off; off >>= 1) {
        d1 += __shfl_xor_sync(0xffffffffu, d1, off);
        d2 += __shfl_xor_sync(0xffffffffu, d2, off);
    }
    if (lane == 0) { g_s1[warp] = d1; g_s2[warp] = d2; }
}

// ---------------- softmax stats from bitmask -------------------------------
__global__ void stats_kernel(const uint32_t* __restrict__ bits)
{
    int warp_in = threadIdx.x >> 5;
    int lane = threadIdx.x & 31;
    int row = blockIdx.x * 8 + warp_in;
    int b = row >> 10;
    uint32_t w = bits[(size_t)row * 32 + lane];
    const float* s2b = g_s2 + (b << 10);
    float s1v = g_s1[row];
    float e[32];
    float m = -INFINITY;
#pragma unroll
    for (int jj = 0; jj < 32; jj++) {
        int j = jj * 32 + lane;
        uint32_t wj = __shfl_sync(0xffffffffu, w, jj);
        float t = s1v + s2b[j];
        t = (t >= 0.f) ? t : LALPHA * t;
        t = ((wj >> lane) & 1u) ? t : NEGV;
        e[jj] = t;
        m = fmaxf(m, t);
    }
#pragma unroll
    for (int off = 16; off; off >>= 1)
        m = fmaxf(m, __shfl_xor_sync(0xffffffffu, m, off));
    float l = 0.f;
#pragma unroll
    for (int jj = 0; jj < 32; jj++) l += __expf(e[jj] - m);
#pragma unroll
    for (int off = 16; off; off >>= 1)
        l += __shfl_xor_sync(0xffffffffu, l, off);
    if (lane == 0) { g_m[row] = m; g_linv[row] = 1.f / l; }
}

// ---------------- attention: out = relu(softmax(e) @ h) --------------------
// Block: 128 i-rows x 256 feats. P built from bitmask + rank-1 scores.
__global__ void __launch_bounds__(512, 1) attn_mma_kernel(
    const uint32_t* __restrict__ bits, const bf16* __restrict__ Hh,
    const bf16* __restrict__ Hl, float* __restrict__ outF,
    bf16* __restrict__ Ohi, bf16* __restrict__ Olo)
{
    extern __shared__ __align__(1024) char smem[];
    const int P_HI = 0, P_LO = 16384, H_HI = 32768, H_LO = 65536, S2 = 98304;
    uint32_t sb = su32(smem);
    int tid = threadIdx.x, lane = tid & 31, w = tid >> 5;
    int wm = w >> 2, wn = w & 3;
    int b = blockIdx.x >> 3;
    int i0 = (blockIdx.x & 7) << 7;

    float* s2s = (float*)(smem + S2);
#pragma unroll
    for (int i = tid; i < NN; i += 512) s2s[i] = g_s2[b * NN + i];

    int prow = tid >> 2;
    int pj = (tid & 3) * 16;
    int growi = b * NN + i0 + prow;
    float s1v = g_s1[growi];
    float mv = g_m[growi];
    const uint32_t* brow = bits + (size_t)growi * 32;

    float acc[2][8][4];
#pragma unroll
    for (int h = 0; h < 2; h++)
#pragma unroll
        for (int t = 0; t < 8; t++)
#pragma unroll
            for (int e = 0; e < 4; e++) acc[h][t][e] = 0.f;

    for (int c = 0; c < 16; c++) {
        int j0 = c << 6;
        __syncthreads();
        // ---- build P tile 128x64 ----
        {
            uint32_t word = brow[(j0 >> 5) + (pj >> 5)];
            int bitbase = pj & 31;
            uint4 hw, lw;
            uint32_t* hp = (uint32_t*)&hw;
            uint32_t* lp = (uint32_t*)&lw;
            uint4 hw2, lw2;
            uint32_t* hp2 = (uint32_t*)&hw2;
            uint32_t* lp2 = (uint32_t*)&lw2;
#pragma unroll
            for (int q = 0; q < 8; q++) {
                float e0 = s1v + s2s[j0 + pj + 2 * q];
                float e1 = s1v + s2s[j0 + pj + 2 * q + 1];
                e0 = (e0 >= 0.f) ? e0 : LALPHA * e0;
                e1 = (e1 >= 0.f) ? e1 : LALPHA * e1;
                float p0 = ((word >> (bitbase + 2 * q)) & 1u) ? __expf(e0 - mv) : 0.f;
                float p1 = ((word >> (bitbase + 2 * q + 1)) & 1u) ? __expf(e1 - mv) : 0.f;
                uint32_t hww, lww;
                split2(p0, p1, hww, lww);
                if (q < 4) { hp[q] = hww; lp[q] = lww; }
                else { hp2[q - 4] = hww; lp2[q - 4] = lww; }
            }
            // NOTE: swz is NOT additive over +16 — compute both offsets
            // through the swizzle (this was the round-6 correctness bug).
            uint32_t o = (uint32_t)prow * 128 + pj * 2;
            uint32_t so0 = swz(o);
            uint32_t so1 = swz(o + 16);
            *(uint4*)(smem + P_HI + so0) = hw;
            *(uint4*)(smem + P_LO + so0) = lw;
            *(uint4*)(smem + P_HI + so1) = hw2;
            *(uint4*)(smem + P_LO + so1) = lw2;
        }
        // ---- load H tile 64x256 (4 panels) ----
#pragma unroll
        for (int i = tid; i < 2048; i += 512) {
            int r = i >> 5, c32 = i & 31;
            int p = c32 >> 3, cc = c32 & 7;
            size_t g = (size_t)(b * NN + j0 + r) * 256 + c32 * 8;
            uint32_t so = p * 8192 + swz(r * 128 + cc * 16);
            *(uint4*)(smem + H_HI + so) = *(const uint4*)(Hh + g);
            *(uint4*)(smem + H_LO + so) = *(const uint4*)(Hl + g);
        }
        __syncthreads();
        mma_chunk(sb + P_HI, sb + P_LO, sb + H_HI + wn * 8192,
                  sb + H_LO + wn * 8192, wm, lane, acc);
    }

    // epilogue: *1/l, ReLU, fp32 out (optional) + bf16 split
    int grp = lane >> 2, qp = lane & 3;
#pragma unroll
    for (int h = 0; h < 2; h++) {
        int mloc = i0 + wm * 32 + h * 16 + grp;
        float li0 = g_linv[b * NN + mloc];
        float li1 = g_linv[b * NN + mloc + 8];
        size_t rb0 = (size_t)(b * NN + mloc) * HH;
        size_t rb1 = (size_t)(b * NN + mloc + 8) * HH;
#pragma unroll
        for (int t = 0; t < 8; t++) {
            int n = wn * 64 + t * 8 + qp * 2;
            float v00 = fmaxf(acc[h][t][0] * li0, 0.f);
            float v01 = fmaxf(acc[h][t][1] * li0, 0.f);
            float v10 = fmaxf(acc[h][t][2] * li1, 0.f);
            float v11 = fmaxf(acc[h][t][3] * li1, 0.f);
            if (outF) {
                float2 f0 = {v00, v01}, f1 = {v10, v11};
                *(float2*)(outF + rb0 + n) = f0;
                *(float2*)(outF + rb1 + n) = f1;
            }
            uint32_t hw, lw;
            split2(v00, v01, hw, lw);
            *(uint32_t*)(Ohi + rb0 + n) = hw;
            *(uint32_t*)(Olo + rb0 + n) = lw;
            split2(v10, v11, hw, lw);
            *(uint32_t*)(Ohi + rb1 + n) = hw;
            *(uint32_t*)(Olo + rb1 + n) = lw;
        }
    }
}

// ---------------- pooling + MLP --------------------------------------------
__global__ void zero_pool_kernel()
{
    int i = blockIdx.x * blockDim.x + threadIdx.x;
    if (i < BB * HH) { g_sum[i] = 0.f; g_max[i] = 0.f; }
}

__global__ void pool_kernel(const float* __restrict__ x)
{
    int b = blockIdx.x >> 3;
    int seg = blockIdx.x & 7;
    int t = threadIdx.x;
    const float* xb = x + ((size_t)b * NN + seg * 128) * HH + t;
    float s = 0.f, mx = 0.f;
#pragma unroll 4
    for (int i = 0; i < 128; i++) {
        float v = xb[(size_t)i * HH];
        s += v;
        mx = fmaxf(mx, v);
    }
    atomicAdd(&g_sum[b * HH + t], s);
    atomicMax((int*)&g_max[b * HH + t], __float_as_int(mx));
}

__global__ void mlp_kernel(const float* __restrict__ W1,
                           const float* __restrict__ b1,
                           const float* __restrict__ W2,
                           const float* __restrict__ b2,
                           float* __restrict__ gout)
{
    __shared__ float p[HH];
    __shared__ float y1[HH];
    int b = blockIdx.x, t = threadIdx.x;
    p[t] = g_sum[b * HH + t] * (1.f / (float)NN) + g_max[b * HH + t];
    __syncthreads();
    float acc = b1[t];
#pragma unroll 4
    for (int k = 0; k < HH; k++)
        acc = fmaf(p[k], W1[(size_t)k * HH + t], acc);
    y1[t] = fmaxf(acc, 0.f);
    __syncthreads();
    float acc2 = b2[t];
#pragma unroll 4
    for (int k = 0; k < HH; k++)
        acc2 = fmaf(y1[k], W2[(size_t)k * HH + t], acc2);
    gout[b * HH + t] = acc2;
}

// ---------------- launch ---------------------------------------------------
extern "C" void kernel_launch(void* const* d_in, const int* in_sizes, int n_in,
                              void* d_out, int out_size)
{
    const float* nf   = (const float*)d_in[0];
    const float* adj  = (const float*)d_in[1];
    const float* embW = (const float*)d_in[2];
    const float* embb = (const float*)d_in[3];
    const float* W0   = (const float*)d_in[4];
    const float* a10  = (const float*)d_in[5];
    const float* a20  = (const float*)d_in[6];
    const float* W1   = (const float*)d_in[7];
    const float* a11  = (const float*)d_in[8];
    const float* a21  = (const float*)d_in[9];
    const float* gW1  = (const float*)d_in[10];
    const float* gb1  = (const float*)d_in[11];
    const float* gW2  = (const float*)d_in[12];
    const float* gb2  = (const float*)d_in[13];

    float* outx = (float*)d_out;
    float* outg = outx + (size_t)BB * NN * HH;

    float* hp;
    bf16 *ahi, *alo, *chi, *clo, *bhi, *blo, *whi, *wlo;
    uint32_t* bitsp;
    cudaGetSymbolAddress((void**)&hp, g_h);
    cudaGetSymbolAddress((void**)&ahi, g_ahi);
    cudaGetSymbolAddress((void**)&alo, g_alo);
    cudaGetSymbolAddress((void**)&chi, g_chi);
    cudaGetSymbolAddress((void**)&clo, g_clo);
    cudaGetSymbolAddress((void**)&bhi, g_bhi);
    cudaGetSymbolAddress((void**)&blo, g_blo);
    cudaGetSymbolAddress((void**)&whi, g_whi);
    cudaGetSymbolAddress((void**)&wlo, g_wlo);
    cudaGetSymbolAddress((void**)&bitsp, g_adjbits);

    const int SM_G = 98304;            // gemm smem
    const int SM_A = 102400;           // attn smem (incl. s2 stage)
    cudaFuncSetAttribute(gemm_mma_kernel,
                         cudaFuncAttributeMaxDynamicSharedMemorySize, SM_G);
    cudaFuncSetAttribute(attn_mma_kernel,
                         cudaFuncAttributeMaxDynamicSharedMemorySize, SM_A);

    const int M = BB * NN;

    // adjacency -> bitmask (read adj floats exactly once)
    packbits_kernel<<<M / 8, 256>>>(adj, bitsp);

    // ---- embed: x = nf @ embW + embb ----
    split_kernel<<<(M * FIN / 4 + 255) / 256, 256>>>(nf, ahi, alo, M * FIN / 4);
    split_kernel<<<(FIN * HH / 4 + 255) / 256, 256>>>(embW, whi, wlo,
                                                      FIN * HH / 4);
    gemm_mma_kernel<<<M / 128, 512, SM_G>>>(ahi, alo, whi, wlo, embb, nullptr,
                                            chi, clo, FIN);

    // ---- GAT layer 0 ----
    split_kernel<<<(HH * HH / 4 + 255) / 256, 256>>>(W0, whi, wlo, HH * HH / 4);
    gemm_mma_kernel<<<M / 128, 512, SM_G>>>(chi, clo, whi, wlo, nullptr, hp,
                                            bhi, blo, HH);
    rowdot_kernel<<<M / 8, 256>>>(hp, a10, a20);
    stats_kernel<<<M / 8, 256>>>(bitsp);
    attn_mma_kernel<<<BB * 8, 512, SM_A>>>(bitsp, bhi, blo, nullptr, ahi, alo);

    // ---- GAT layer 1 ----
    split_kernel<<<(HH * HH / 4 + 255) / 256, 256>>>(W1, whi, wlo, HH * HH / 4);
    gemm_mma_kernel<<<M / 128, 512, SM_G>>>(ahi, alo, whi, wlo, nullptr, hp,
                                            bhi, blo, HH);
    rowdot_kernel<<<M / 8, 256>>>(hp, a11, a21);
    stats_kernel<<<M / 8, 256>>>(bitsp);
    attn_mma_kernel<<<BB * 8, 512, SM_A>>>(bitsp, bhi, blo, outx, chi, clo);

    // ---- pooling + MLP ----
    zero_pool_kernel<<<(BB * HH + 255) / 256, 256>>>();
    pool_kernel<<<BB * 8, 256>>>(outx);
    mlp_kernel<<<BB, 256>>>(gW1, gb1, gW2, gb2, outg);
}

// round 8
// speedup vs baseline: 4.1475x; 1.0565x over previous
#include <cuda_runtime.h>
#include <cuda_bf16.h>
#include <math.h>
#include <stdint.h>

#define BB 16
#define NN 1024
#define FIN 64
#define HH 256
#define NEGV (-9e15f)
#define LALPHA 0.2f

typedef __nv_bfloat16 bf16;

// ---------------- scratch (device globals: no allocation allowed) ----------
__device__ __align__(256) bf16 g_ahi[BB * NN * HH];
__device__ __align__(256) bf16 g_alo[BB * NN * HH];
__device__ __align__(256) bf16 g_chi[BB * NN * HH];
__device__ __align__(256) bf16 g_clo[BB * NN * HH];
__device__ __align__(256) bf16 g_bhi[BB * NN * HH];
__device__ __align__(256) bf16 g_blo[BB * NN * HH];
__device__ __align__(256) bf16 g_whi[HH * HH];
__device__ __align__(256) bf16 g_wlo[HH * HH];
__device__ __align__(256) uint32_t g_adjbits[BB * NN * (NN / 32)];
__device__ __align__(256) float g_s1[BB * NN];
__device__ __align__(256) float g_s2[BB * NN];
__device__ __align__(256) float g_m[BB * NN];
__device__ __align__(256) float g_linv[BB * NN];
__device__ __align__(256) float g_sum[BB * HH];
__device__ __align__(256) float g_max[BB * HH];

// ---------------- helpers --------------------------------------------------
__device__ __forceinline__ uint32_t swz(uint32_t o) {
    return o ^ ((o >> 3) & 0x70);
}
__device__ __forceinline__ uint32_t su32(const void* p) {
    uint32_t a;
    asm("{ .reg .u64 t; cvta.to.shared.u64 t, %1; cvt.u32.u64 %0, t; }"
        : "=r"(a) : "l"(p));
    return a;
}
#define CP16(d, s)                                                            \
    asm volatile("cp.async.cg.shared.global [%0], [%1], 16;" ::"r"(d), "l"(s))
#define CPCOMMIT() asm volatile("cp.async.commit_group;" ::: "memory")
#define CPWAIT0() asm volatile("cp.async.wait_group 0;" ::: "memory")

__device__ __forceinline__ void ldsm4(uint32_t addr, uint32_t* r) {
    asm volatile("ldmatrix.sync.aligned.m8n8.x4.shared.b16 {%0,%1,%2,%3}, [%4];"
                 : "=r"(r[0]), "=r"(r[1]), "=r"(r[2]), "=r"(r[3]) : "r"(addr));
}
__device__ __forceinline__ void ldsm4t(uint32_t addr, uint32_t* r) {
    asm volatile("ldmatrix.sync.aligned.m8n8.x4.trans.shared.b16 {%0,%1,%2,%3}, [%4];"
                 : "=r"(r[0]), "=r"(r[1]), "=r"(r[2]), "=r"(r[3]) : "r"(addr));
}
__device__ __forceinline__ void mma16816(float* c, const uint32_t* a,
                                         const uint32_t* b) {
    asm volatile(
        "mma.sync.aligned.m16n8k16.row.col.f32.bf16.bf16.f32 "
        "{%0,%1,%2,%3}, {%4,%5,%6,%7}, {%8,%9}, {%0,%1,%2,%3};"
        : "+f"(c[0]), "+f"(c[1]), "+f"(c[2]), "+f"(c[3])
        : "r"(a[0]), "r"(a[1]), "r"(a[2]), "r"(a[3]), "r"(b[0]), "r"(b[1]));
}

// warp mma over one 64-k chunk: A tile [128][64], B panel [64][64], 3-pass.
__device__ __forceinline__ void mma_chunk(uint32_t aHi, uint32_t aLo,
                                          uint32_t bHi, uint32_t bLo,
                                          int wm, int lane,
                                          float acc[2][8][4])
{
    int rA = lane & 15;
    int cA = (lane >> 4) * 16;
#pragma unroll
    for (int ks = 0; ks < 4; ks++) {
        uint32_t ah[2][4], al[2][4], bb[4][4];
#pragma unroll
        for (int h = 0; h < 2; h++) {
            uint32_t off = swz((uint32_t)(wm * 32 + h * 16 + rA) * 128 +
                               ks * 32 + cA);
            ldsm4(aHi + off, ah[h]);
            ldsm4(aLo + off, al[h]);
        }
#pragma unroll
        for (int t = 0; t < 4; t++) {
            uint32_t off = swz((uint32_t)(ks * 16 + rA) * 128 + t * 32 + cA);
            ldsm4t(bHi + off, bb[t]);
        }
#pragma unroll
        for (int h = 0; h < 2; h++)
#pragma unroll
            for (int t = 0; t < 4; t++) {
                mma16816(acc[h][2 * t], ah[h], bb[t]);         // hh
                mma16816(acc[h][2 * t + 1], ah[h], bb[t] + 2);
                mma16816(acc[h][2 * t], al[h], bb[t]);         // lo*hi
                mma16816(acc[h][2 * t + 1], al[h], bb[t] + 2);
            }
#pragma unroll
        for (int t = 0; t < 4; t++) {
            uint32_t off = swz((uint32_t)(ks * 16 + rA) * 128 + t * 32 + cA);
            ldsm4t(bLo + off, bb[t]);
        }
#pragma unroll
        for (int h = 0; h < 2; h++)
#pragma unroll
            for (int t = 0; t < 4; t++) {
                mma16816(acc[h][2 * t], ah[h], bb[t]);         // hi*lo
                mma16816(acc[h][2 * t + 1], ah[h], bb[t] + 2);
            }
    }
}

__device__ __forceinline__ void split2(float v0, float v1, uint32_t& hw,
                                       uint32_t& lw) {
    __nv_bfloat162 h2 = __floats2bfloat162_rn(v0, v1);
    float r0 = v0 - __bfloat162float(h2.x);
    float r1 = v1 - __bfloat162float(h2.y);
    __nv_bfloat162 l2 = __floats2bfloat162_rn(r0, r1);
    hw = *(uint32_t*)&h2;
    lw = *(uint32_t*)&l2;
}

// ---------------- prep kernels ---------------------------------------------
__global__ void packbits_kernel(const float* __restrict__ adj,
                                uint32_t* __restrict__ bits)
{
    int row = (blockIdx.x * blockDim.x + threadIdx.x) >> 5;
    int lane = threadIdx.x & 31;
    if (row >= BB * NN) return;
    const float* ar = adj + (size_t)row * NN;
    uint32_t myword = 0;
#pragma unroll
    for (int wd = 0; wd < 32; wd++) {
        uint32_t v = __ballot_sync(0xffffffffu, ar[wd * 32 + lane] > 0.f);
        if (lane == wd) myword = v;
    }
    bits[(size_t)row * 32 + lane] = myword;
}

__global__ void split_kernel(const float* __restrict__ X,
                             bf16* __restrict__ Xh, bf16* __restrict__ Xl,
                             int n4)
{
    int i = blockIdx.x * blockDim.x + threadIdx.x;
    if (i >= n4) return;
    float4 v = *(const float4*)(X + (size_t)i * 4);
    uint2 hw, lw;
    split2(v.x, v.y, hw.x, lw.x);
    split2(v.z, v.w, hw.y, lw.y);
    *(uint2*)(Xh + (size_t)i * 4) = hw;
    *(uint2*)(Xl + (size_t)i * 4) = lw;
}

// ---------------- pipelined GEMM: C = A[M,K] @ B[K,256] (+bias) ------------
// 2-stage cp.async pipeline. Optional fused rowdot: s1 = C.a1, s2 = C.a2.
// Stage layout (98304 B): A_HI 0 | A_LO 16384 | B_HI 32768 | B_LO 65536.
__device__ __forceinline__ void gemm_load_chunk(
    uint32_t sb, int st, int tid, int m0, int k0,
    const bf16* Ah, const bf16* Al, const bf16* Bh, const bf16* Bl, int K)
{
    uint32_t s0 = sb + st * 98304;
#pragma unroll
    for (int i = tid; i < 1024; i += 512) {
        int r = i >> 3, cc = i & 7;
        size_t g = (size_t)(m0 + r) * K + k0 + cc * 8;
        uint32_t so = s0 + swz(r * 128 + cc * 16);
        CP16(so, Ah + g);
        CP16(so + 16384, Al + g);
    }
#pragma unroll
    for (int i = tid; i < 2048; i += 512) {
        int r = i >> 5, c32 = i & 31;
        int p = c32 >> 3, cc = c32 & 7;
        size_t g = (size_t)(k0 + r) * 256 + c32 * 8;
        uint32_t so = s0 + 32768 + p * 8192 + swz(r * 128 + cc * 16);
        CP16(so, Bh + g);
        CP16(so + 32768, Bl + g);
    }
}

__global__ void __launch_bounds__(512, 1) gemm_mma_kernel(
    const bf16* __restrict__ Ah, const bf16* __restrict__ Al,
    const bf16* __restrict__ Bh, const bf16* __restrict__ Bl,
    const float* __restrict__ bias, const float* __restrict__ a1,
    const float* __restrict__ a2, bf16* __restrict__ Chi,
    bf16* __restrict__ Clo, int K)
{
    extern __shared__ __align__(1024) char smem[];
    uint32_t sb = su32(smem);
    int tid = threadIdx.x, lane = tid & 31, w = tid >> 5;
    int wm = w >> 2, wn = w & 3;
    int m0 = blockIdx.x * 128;
    int nch = K >> 6;

    float acc[2][8][4];
#pragma unroll
    for (int h = 0; h < 2; h++)
#pragma unroll
        for (int t = 0; t < 8; t++)
#pragma unroll
            for (int e = 0; e < 4; e++) acc[h][t][e] = 0.f;

    gemm_load_chunk(sb, 0, tid, m0, 0, Ah, Al, Bh, Bl, K);
    CPCOMMIT();

    for (int c = 0; c < nch; c++) {
        int st = c & 1;
        CPWAIT0();
        __syncthreads();
        if (c + 1 < nch) {
            gemm_load_chunk(sb, st ^ 1, tid, m0, (c + 1) << 6, Ah, Al, Bh, Bl, K);
            CPCOMMIT();
        }
        mma_chunk(sb + st * 98304, sb + st * 98304 + 16384,
                  sb + st * 98304 + 32768 + wn * 8192,
                  sb + st * 98304 + 65536 + wn * 8192, wm, lane, acc);
    }

    // fused rowdot scratch
    float* s1s = (float*)(smem + 196608);
    float* s2s = s1s + 128;
    if (tid < 256) s1s[tid] = 0.f;
    __syncthreads();

    int grp = lane >> 2, qp = lane & 3;
#pragma unroll
    for (int h = 0; h < 2; h++) {
        int mA = m0 + wm * 32 + h * 16 + grp;
        float p1a = 0.f, p1b = 0.f, p2a = 0.f, p2b = 0.f;
#pragma unroll
        for (int t = 0; t < 8; t++) {
            int n = wn * 64 + t * 8 + qp * 2;
            float b0 = bias ? bias[n] : 0.f;
            float b1 = bias ? bias[n + 1] : 0.f;
            float v00 = acc[h][t][0] + b0, v01 = acc[h][t][1] + b1;
            float v10 = acc[h][t][2] + b0, v11 = acc[h][t][3] + b1;
            size_t o0 = (size_t)mA * HH + n;
            size_t o1 = (size_t)(mA + 8) * HH + n;
            uint32_t hw, lw;
            split2(v00, v01, hw, lw);
            *(uint32_t*)(Chi + o0) = hw;
            *(uint32_t*)(Clo + o0) = lw;
            split2(v10, v11, hw, lw);
            *(uint32_t*)(Chi + o1) = hw;
            *(uint32_t*)(Clo + o1) = lw;
            if (a1) {
                float a1v0 = a1[n], a1v1 = a1[n + 1];
                float a2v0 = a2[n], a2v1 = a2[n + 1];
                p1a += v00 * a1v0 + v01 * a1v1;
                p1b += v10 * a1v0 + v11 * a1v1;
                p2a += v00 * a2v0 + v01 * a2v1;
                p2b += v10 * a2v0 + v11 * a2v1;
            }
        }
        if (a1) {
            int lr = wm * 32 + h * 16 + grp;
            atomicAdd(&s1s[lr], p1a);
            atomicAdd(&s1s[lr + 8], p1b);
            atomicAdd(&s2s[lr], p2a);
            atomicAdd(&s2s[lr + 8], p2b);
        }
    }
    if (a1) {
        __syncthreads();
        if (tid < 128) {
            g_s1[m0 + tid] = s1s[tid];
            g_s2[m0 + tid] = s2s[tid];
        }
    }
}

// ---------------- softmax stats from bitmask -------------------------------
__global__ void stats_kernel(const uint32_t* __restrict__ bits)
{
    int warp_in = threadIdx.x >> 5;
    int lane = threadIdx.x & 31;
    int row = blockIdx.x * 8 + warp_in;
    int b = row >> 10;
    uint32_t w = bits[(size_t)row * 32 + lane];
    const float* s2b = g_s2 + (b << 10);
    float s1v = g_s1[row];
    float e[32];
    float m = -INFINITY;
#pragma unroll
    for (int jj = 0; jj < 32; jj++) {
        int j = jj * 32 + lane;
        uint32_t wj = __shfl_sync(0xffffffffu, w, jj);
        float t = s1v + s2b[j];
        t = (t >= 0.f) ? t : LALPHA * t;
        t = ((wj >> lane) & 1u) ? t : NEGV;
        e[jj] = t;
        m = fmaxf(m, t);
    }
#pragma unroll
    for (int off = 16; off; off >>= 1)
        m = fmaxf(m, __shfl_xor_sync(0xffffffffu, m, off));
    float l = 0.f;
#pragma unroll
    for (int jj = 0; jj < 32; jj++) l += __expf(e[jj] - m);
#pragma unroll
    for (int off = 16; off; off >>= 1)
        l += __shfl_xor_sync(0xffffffffu, l, off);
    if (lane == 0) { g_m[row] = m; g_linv[row] = 1.f / l; }
}

// ---------------- pipelined attention: out = relu(softmax(e) @ h) ----------
// smem: P stages 2x32768 @0 | H stages 2x65536 @65536 | s2 @196608 (4 KB).
__device__ __forceinline__ void attn_load_h(
    uint32_t sb, int st, int tid, int b, int j0,
    const bf16* Hh, const bf16* Hl)
{
    uint32_t s0 = sb + 65536 + st * 65536;
#pragma unroll
    for (int i = tid; i < 2048; i += 512) {
        int r = i >> 5, c32 = i & 31;
        int p = c32 >> 3, cc = c32 & 7;
        size_t g = (size_t)(b * NN + j0 + r) * 256 + c32 * 8;
        uint32_t so = s0 + p * 8192 + swz(r * 128 + cc * 16);
        CP16(so, Hh + g);
        CP16(so + 32768, Hl + g);
    }
}

__global__ void __launch_bounds__(512, 1) attn_mma_kernel(
    const uint32_t* __restrict__ bits, const bf16* __restrict__ Hh,
    const bf16* __restrict__ Hl, float* __restrict__ outF,
    bf16* __restrict__ Ohi, bf16* __restrict__ Olo)
{
    extern __shared__ __align__(1024) char smem[];
    uint32_t sb = su32(smem);
    int tid = threadIdx.x, lane = tid & 31, w = tid >> 5;
    int wm = w >> 2, wn = w & 3;
    int b = blockIdx.x >> 3;
    int i0 = (blockIdx.x & 7) << 7;

    float* s2s = (float*)(smem + 196608);

    int prow = tid >> 2;
    int pj = (tid & 3) * 16;
    int growi = b * NN + i0 + prow;
    float s1v = g_s1[growi];
    float mv = g_m[growi];
    const uint32_t* brow = bits + (size_t)growi * 32;

    // prologue: stage s2, start H0 loads
    for (int i = tid; i < NN; i += 512) s2s[i] = g_s2[b * NN + i];
    attn_load_h(sb, 0, tid, b, 0, Hh, Hl);
    CPCOMMIT();
    __syncthreads();   // s2s visible

#define BUILD_P(cc, st)                                                        \
    do {                                                                       \
        int j0_ = (cc) << 6;                                                   \
        uint32_t word = brow[(j0_ >> 5) + (pj >> 5)];                          \
        int bitbase = pj & 31;                                                 \
        uint4 hw, lw, hw2, lw2;                                                \
        uint32_t* hp = (uint32_t*)&hw;                                         \
        uint32_t* lp = (uint32_t*)&lw;                                         \
        uint32_t* hp2 = (uint32_t*)&hw2;                                       \
        uint32_t* lp2 = (uint32_t*)&lw2;                                       \
        _Pragma("unroll") for (int q = 0; q < 8; q++) {                        \
            float e0 = s1v + s2s[j0_ + pj + 2 * q];                            \
            float e1 = s1v + s2s[j0_ + pj + 2 * q + 1];                        \
            e0 = (e0 >= 0.f) ? e0 : LALPHA * e0;                               \
            e1 = (e1 >= 0.f) ? e1 : LALPHA * e1;                               \
            float p0 = ((word >> (bitbase + 2 * q)) & 1u) ? __expf(e0 - mv) : 0.f; \
            float p1 = ((word >> (bitbase + 2 * q + 1)) & 1u) ? __expf(e1 - mv) : 0.f; \
            uint32_t hww, lww;                                                 \
            split2(p0, p1, hww, lww);                                          \
            if (q < 4) { hp[q] = hww; lp[q] = lww; }                           \
            else { hp2[q - 4] = hww; lp2[q - 4] = lww; }                       \
        }                                                                      \
        uint32_t o = (uint32_t)prow * 128 + pj * 2;                            \
        uint32_t so0 = swz(o), so1 = swz(o + 16);                              \
        char* pb = smem + (st) * 32768;                                        \
        *(uint4*)(pb + so0) = hw;                                              \
        *(uint4*)(pb + 16384 + so0) = lw;                                      \
        *(uint4*)(pb + so1) = hw2;                                             \
        *(uint4*)(pb + 16384 + so1) = lw2;                                     \
    } while (0)

    BUILD_P(0, 0);

    float acc[2][8][4];
#pragma unroll
    for (int h = 0; h < 2; h++)
#pragma unroll
        for (int t = 0; t < 8; t++)
#pragma unroll
            for (int e = 0; e < 4; e++) acc[h][t][e] = 0.f;

    for (int c = 0; c < 16; c++) {
        int st = c & 1;
        CPWAIT0();
        __syncthreads();          // H[c] + P[c] ready; prior mma done
        if (c < 15) {
            attn_load_h(sb, st ^ 1, tid, b, (c + 1) << 6, Hh, Hl);
            CPCOMMIT();
            BUILD_P(c + 1, st ^ 1);
        }
        mma_chunk(sb + st * 32768, sb + st * 32768 + 16384,
                  sb + 65536 + st * 65536 + wn * 8192,
                  sb + 65536 + st * 65536 + 32768 + wn * 8192, wm, lane, acc);
    }
#undef BUILD_P

    // epilogue: *1/l, ReLU, optional fp32 out + bf16 split
    int grp = lane >> 2, qp = lane & 3;
#pragma unroll
    for (int h = 0; h < 2; h++) {
        int mloc = i0 + wm * 32 + h * 16 + grp;
        float li0 = g_linv[b * NN + mloc];
        float li1 = g_linv[b * NN + mloc + 8];
        size_t rb0 = (size_t)(b * NN + mloc) * HH;
        size_t rb1 = (size_t)(b * NN + mloc + 8) * HH;
#pragma unroll
        for (int t = 0; t < 8; t++) {
            int n = wn * 64 + t * 8 + qp * 2;
            float v00 = fmaxf(acc[h][t][0] * li0, 0.f);
            float v01 = fmaxf(acc[h][t][1] * li0, 0.f);
            float v10 = fmaxf(acc[h][t][2] * li1, 0.f);
            float v11 = fmaxf(acc[h][t][3] * li1, 0.f);
            if (outF) {
                float2 f0 = {v00, v01}, f1 = {v10, v11};
                *(float2*)(outF + rb0 + n) = f0;
                *(float2*)(outF + rb1 + n) = f1;
            }
            uint32_t hw, lw;
            split2(v00, v01, hw, lw);
            *(uint32_t*)(Ohi + rb0 + n) = hw;
            *(uint32_t*)(Olo + rb0 + n) = lw;
            split2(v10, v11, hw, lw);
            *(uint32_t*)(Ohi + rb1 + n) = hw;
            *(uint32_t*)(Olo + rb1 + n) = lw;
        }
    }
}

// ---------------- pooling + MLP --------------------------------------------
__global__ void zero_pool_kernel()
{
    int i = blockIdx.x * blockDim.x + threadIdx.x;
    if (i < BB * HH) { g_sum[i] = 0.f; g_max[i] = 0.f; }
}

__global__ void pool_kernel(const float* __restrict__ x)
{
    int b = blockIdx.x >> 3;
    int seg = blockIdx.x & 7;
    int t = threadIdx.x;
    const float* xb = x + ((size_t)b * NN + seg * 128) * HH + t;
    float s = 0.f, mx = 0.f;
#pragma unroll 4
    for (int i = 0; i < 128; i++) {
        float v = xb[(size_t)i * HH];
        s += v;
        mx = fmaxf(mx, v);
    }
    atomicAdd(&g_sum[b * HH + t], s);
    atomicMax((int*)&g_max[b * HH + t], __float_as_int(mx));
}

__global__ void mlp_kernel(const float* __restrict__ W1,
                           const float* __restrict__ b1,
                           const float* __restrict__ W2,
                           const float* __restrict__ b2,
                           float* __restrict__ gout)
{
    __shared__ float p[HH];
    __shared__ float y1[HH];
    int b = blockIdx.x, t = threadIdx.x;
    p[t] = g_sum[b * HH + t] * (1.f / (float)NN) + g_max[b * HH + t];
    __syncthreads();
    float acc = b1[t];
#pragma unroll 4
    for (int k = 0; k < HH; k++)
        acc = fmaf(p[k], W1[(size_t)k * HH + t], acc);
    y1[t] = fmaxf(acc, 0.f);
    __syncthreads();
    float acc2 = b2[t];
#pragma unroll 4
    for (int k = 0; k < HH; k++)
        acc2 = fmaf(y1[k], W2[(size_t)k * HH + t], acc2);
    gout[b * HH + t] = acc2;
}

// ---------------- launch ---------------------------------------------------
extern "C" void kernel_launch(void* const* d_in, const int* in_sizes, int n_in,
                              void* d_out, int out_size)
{
    const float* nf   = (const float*)d_in[0];
    const float* adj  = (const float*)d_in[1];
    const float* embW = (const float*)d_in[2];
    const float* embb = (const float*)d_in[3];
    const float* W0   = (const float*)d_in[4];
    const float* a10  = (const float*)d_in[5];
    const float* a20  = (const float*)d_in[6];
    const float* W1   = (const float*)d_in[7];
    const float* a11  = (const float*)d_in[8];
    const float* a21  = (const float*)d_in[9];
    const float* gW1  = (const float*)d_in[10];
    const float* gb1  = (const float*)d_in[11];
    const float* gW2  = (const float*)d_in[12];
    const float* gb2  = (const float*)d_in[13];

    float* outx = (float*)d_out;
    float* outg = outx + (size_t)BB * NN * HH;

    bf16 *ahi, *alo, *chi, *clo, *bhi, *blo, *whi, *wlo;
    uint32_t* bitsp;
    cudaGetSymbolAddress((void**)&ahi, g_ahi);
    cudaGetSymbolAddress((void**)&alo, g_alo);
    cudaGetSymbolAddress((void**)&chi, g_chi);
    cudaGetSymbolAddress((void**)&clo, g_clo);
    cudaGetSymbolAddress((void**)&bhi, g_bhi);
    cudaGetSymbolAddress((void**)&blo, g_blo);
    cudaGetSymbolAddress((void**)&whi, g_whi);
    cudaGetSymbolAddress((void**)&wlo, g_wlo);
    cudaGetSymbolAddress((void**)&bitsp, g_adjbits);

    const int SM_G = 2 * 98304 + 1024;     // 197632
    const int SM_A = 2 * 32768 + 2 * 65536 + 4096;  // 200704
    cudaFuncSetAttribute(gemm_mma_kernel,
                         cudaFuncAttributeMaxDynamicSharedMemorySize, SM_G);
    cudaFuncSetAttribute(attn_mma_kernel,
                         cudaFuncAttributeMaxDynamicSharedMemorySize, SM_A);

    const int M = BB * NN;

    packbits_kernel<<<M / 8, 256>>>(adj, bitsp);

    // ---- embed: x = nf @ embW + embb ----
    split_kernel<<<(M * FIN / 4 + 255) / 256, 256>>>(nf, ahi, alo, M * FIN / 4);
    split_kernel<<<(FIN * HH / 4 + 255) / 256, 256>>>(embW, whi, wlo,
                                                      FIN * HH / 4);
    gemm_mma_kernel<<<M / 128, 512, SM_G>>>(ahi, alo, whi, wlo, embb,
                                            nullptr, nullptr, chi, clo, FIN);

    // ---- GAT layer 0 ----
    split_kernel<<<(HH * HH / 4 + 255) / 256, 256>>>(W0, whi, wlo, HH * HH / 4);
    gemm_mma_kernel<<<M / 128, 512, SM_G>>>(chi, clo, whi, wlo, nullptr,
                                            a10, a20, bhi, blo, HH);
    stats_kernel<<<M / 8, 256>>>(bitsp);
    attn_mma_kernel<<<BB * 8, 512, SM_A>>>(bitsp, bhi, blo, nullptr, ahi, alo);

    // ---- GAT layer 1 ----
    split_kernel<<<(HH * HH / 4 + 255) / 256, 256>>>(W1, whi, wlo, HH * HH / 4);
    gemm_mma_kernel<<<M / 128, 512, SM_G>>>(ahi, alo, whi, wlo, nullptr,
                                            a11, a21, bhi, blo, HH);
    stats_kernel<<<M / 8, 256>>>(bitsp);
    attn_mma_kernel<<<BB * 8, 512, SM_A>>>(bitsp, bhi, blo, outx, chi, clo);

    // ---- pooling + MLP ----
    zero_pool_kernel<<<(BB * HH + 255) / 256, 256>>>();
    pool_kernel<<<BB * 8, 256>>>(outx);
    mlp_kernel<<<BB, 256>>>(gW1, gb1, gW2, gb2, outg);
}